// round 4
// baseline (speedup 1.0000x reference)
#include <cuda_runtime.h>
#include <cuda_bf16.h>
#include <cstdint>
#include <cstddef>
#include <math.h>

// Problem constants
#define Dm   2048
#define Hh   32
#define DSs  64
#define KK   4
#define EPSf 1e-6f

// Max sizes (B=2, L=4096)
#define BL_MAX  8192
#define P_COLS  (3*Dm)   // 6144

// Scratch layout (floats)
#define OFF_XN     ((size_t)0)
#define OFF_XC     ((size_t)BL_MAX*Dm)                       // 16,777,216
#define OFF_P      (OFF_XC + (size_t)BL_MAX*Dm)              // 33,554,432
#define OFF_GATE   (OFF_P  + (size_t)BL_MAX*P_COLS)          // 83,886,080
#define OFF_MIXED  (OFF_GATE + (size_t)BL_MAX*Dm)            // 100,663,296
#define SCRATCH_FLOATS (OFF_MIXED + (size_t)BL_MAX*Dm)       // 117,440,512

__device__ float g_scratch[SCRATCH_FLOATS];

// ---------------------------------------------------------------------------
// Helpers
// ---------------------------------------------------------------------------
__device__ __forceinline__ uint32_t f2tf32(float f) {
    uint32_t u;
    asm("cvt.rna.tf32.f32 %0, %1;" : "=r"(u) : "f"(f));
    return u;
}

__device__ __forceinline__ void mma_tf32(float* c, const uint32_t* a, const uint32_t* b) {
    asm volatile(
        "mma.sync.aligned.m16n8k8.row.col.f32.tf32.tf32.f32 "
        "{%0,%1,%2,%3}, {%4,%5,%6,%7}, {%8,%9}, {%0,%1,%2,%3};\n"
        : "+f"(c[0]), "+f"(c[1]), "+f"(c[2]), "+f"(c[3])
        : "r"(a[0]), "r"(a[1]), "r"(a[2]), "r"(a[3]),
          "r"(b[0]), "r"(b[1]));
}

__device__ __forceinline__ void cp_async16(void* smem, const void* gmem) {
    uint32_t s = (uint32_t)__cvta_generic_to_shared(smem);
    asm volatile("cp.async.cg.shared.global [%0], [%1], 16;\n" :: "r"(s), "l"(gmem));
}

__device__ __forceinline__ float sigmoidf_(float v) {
    return 1.0f / (1.0f + __expf(-v));
}

// ---------------------------------------------------------------------------
// RMSNorm: xn = norm_w * x / sqrt(mean(x^2)+eps)   (one block per row)
// ---------------------------------------------------------------------------
__global__ void rmsnorm_kernel(const float* __restrict__ x,
                               const float* __restrict__ w,
                               float* __restrict__ xn) {
    size_t row = blockIdx.x;
    const float4* xr = (const float4*)(x + row * Dm);
    float4 v0 = xr[threadIdx.x];
    float4 v1 = xr[threadIdx.x + 256];
    float ss = v0.x*v0.x + v0.y*v0.y + v0.z*v0.z + v0.w*v0.w
             + v1.x*v1.x + v1.y*v1.y + v1.z*v1.z + v1.w*v1.w;
    #pragma unroll
    for (int o = 16; o > 0; o >>= 1) ss += __shfl_xor_sync(0xffffffffu, ss, o);
    __shared__ float red[8];
    if ((threadIdx.x & 31) == 0) red[threadIdx.x >> 5] = ss;
    __syncthreads();
    float tot = red[0] + red[1] + red[2] + red[3] + red[4] + red[5] + red[6] + red[7];
    float inv = rsqrtf(tot * (1.0f / Dm) + EPSf);

    const float4* wr = (const float4*)w;
    float4 w0 = wr[threadIdx.x];
    float4 w1 = wr[threadIdx.x + 256];
    float4 o0, o1;
    o0.x = v0.x * w0.x * inv; o0.y = v0.y * w0.y * inv;
    o0.z = v0.z * w0.z * inv; o0.w = v0.w * w0.w * inv;
    o1.x = v1.x * w1.x * inv; o1.y = v1.y * w1.y * inv;
    o1.z = v1.z * w1.z * inv; o1.w = v1.w * w1.w * inv;
    float4* orow = (float4*)(xn + row * Dm);
    orow[threadIdx.x]       = o0;
    orow[threadIdx.x + 256] = o1;
}

// ---------------------------------------------------------------------------
// Causal depthwise conv (K=4) + SiLU.
// Block: 128 threads over d; each thread walks 256 consecutive l with a
// rolling register window. grid = (D/128, L/256, B)
// ---------------------------------------------------------------------------
__global__ void conv_silu_kernel(const float* __restrict__ xn,
                                 const float* __restrict__ cw,
                                 const float* __restrict__ cb,
                                 float* __restrict__ xc, int L) {
    int d  = blockIdx.x * 128 + threadIdx.x;
    int b  = blockIdx.z;
    int l0 = blockIdx.y * 256;
    float w0 = cw[d*KK + 0], w1 = cw[d*KK + 1], w2 = cw[d*KK + 2], w3 = cw[d*KK + 3];
    float bb = cb[d];
    const float* base = xn + ((size_t)b * L) * Dm + d;
    float* obase      = xc + ((size_t)b * L) * Dm + d;

    float xm3 = (l0 >= 3) ? base[(size_t)(l0 - 3) * Dm] : 0.0f;
    float xm2 = (l0 >= 2) ? base[(size_t)(l0 - 2) * Dm] : 0.0f;
    float xm1 = (l0 >= 1) ? base[(size_t)(l0 - 1) * Dm] : 0.0f;

    for (int l = l0; l < l0 + 256; l++) {
        float xcur = base[(size_t)l * Dm];
        float acc = bb + w0 * xm3 + w1 * xm2 + w2 * xm1 + w3 * xcur;
        float sv = acc * sigmoidf_(acc);   // silu
        obase[(size_t)l * Dm] = sv;
        xm3 = xm2; xm2 = xm1; xm1 = xcur;
    }
}

// ---------------------------------------------------------------------------
// TF32 GEMM: C[M,N] = A[M,K] @ B[K,N] (+bias[n]) (+epilogue)
//   MODE 0: + bias                         (p projection)
//   MODE 1: sigmoid(+ bias)               (gate)
//   MODE 2: + bias + res[m,n]             (output, residual x)
// Tiles: BM=128, BN=128, BK=16, 256 threads (8 warps of 64x32)
// ---------------------------------------------------------------------------
#define GBM 128
#define GBN 128
#define GBK 16
#define SA_STR 20    // BK + 4, conflict-free A fragment loads
#define SB_STR 136   // BN + 8, conflict-free B fragment loads

template<int MODE>
__global__ __launch_bounds__(256)
void gemm_tf32(const float* __restrict__ A, const float* __restrict__ Bw,
               const float* __restrict__ bias, const float* __restrict__ res,
               float* __restrict__ C, int M, int N, int K) {
    __shared__ float sA[2][GBM * SA_STR];   // 20 KB
    __shared__ float sB[2][GBK * SB_STR];   // 17 KB

    int tid  = threadIdx.x;
    int wid  = tid >> 5;
    int lane = tid & 31;
    int wm = (wid & 1) * 64;     // warp row offset within block tile
    int wn = (wid >> 1) * 32;    // warp col offset
    int g = lane >> 2;           // group id (0..7)
    int t = lane & 3;            // thread-in-group (0..3)

    int bm = blockIdx.y * GBM;
    int bn = blockIdx.x * GBN;

    const float* Aptr = A + (size_t)bm * K;
    const float* Bptr = Bw + bn;

    float acc[4][4][4];
    #pragma unroll
    for (int i = 0; i < 4; i++)
        #pragma unroll
        for (int j = 0; j < 4; j++)
            #pragma unroll
            for (int q = 0; q < 4; q++) acc[i][j][q] = 0.0f;

    // Precompute per-thread load coordinates
    int a_r0 = tid >> 2;               // 0..63
    int a_c0 = (tid & 3) * 4;
    int b_r0 = tid >> 5;               // 0..7
    int b_c0 = (tid & 31) * 4;

    int NK = K / GBK;

    // Prologue: load tile 0 into buffer 0
    {
        int k0 = 0;
        cp_async16(&sA[0][a_r0 * SA_STR + a_c0],        Aptr + (size_t)a_r0 * K + k0 + a_c0);
        cp_async16(&sA[0][(a_r0 + 64) * SA_STR + a_c0], Aptr + (size_t)(a_r0 + 64) * K + k0 + a_c0);
        cp_async16(&sB[0][b_r0 * SB_STR + b_c0],        Bptr + (size_t)(k0 + b_r0) * N + b_c0);
        cp_async16(&sB[0][(b_r0 + 8) * SB_STR + b_c0],  Bptr + (size_t)(k0 + b_r0 + 8) * N + b_c0);
        asm volatile("cp.async.commit_group;\n" ::);
    }

    for (int kt = 0; kt < NK; kt++) {
        int buf = kt & 1;
        if (kt + 1 < NK) {
            int k0 = (kt + 1) * GBK;
            int nb = buf ^ 1;
            cp_async16(&sA[nb][a_r0 * SA_STR + a_c0],        Aptr + (size_t)a_r0 * K + k0 + a_c0);
            cp_async16(&sA[nb][(a_r0 + 64) * SA_STR + a_c0], Aptr + (size_t)(a_r0 + 64) * K + k0 + a_c0);
            cp_async16(&sB[nb][b_r0 * SB_STR + b_c0],        Bptr + (size_t)(k0 + b_r0) * N + b_c0);
            cp_async16(&sB[nb][(b_r0 + 8) * SB_STR + b_c0],  Bptr + (size_t)(k0 + b_r0 + 8) * N + b_c0);
            asm volatile("cp.async.commit_group;\n" ::);
            asm volatile("cp.async.wait_group 1;\n" ::);
        } else {
            asm volatile("cp.async.wait_group 0;\n" ::);
        }
        __syncthreads();

        #pragma unroll
        for (int k8 = 0; k8 < 2; k8++) {
            uint32_t af[4][4], bf[4][2];
            #pragma unroll
            for (int mt = 0; mt < 4; mt++) {
                int r = wm + mt * 16 + g;
                int c = k8 * 8 + t;
                af[mt][0] = f2tf32(sA[buf][r * SA_STR + c]);
                af[mt][1] = f2tf32(sA[buf][(r + 8) * SA_STR + c]);
                af[mt][2] = f2tf32(sA[buf][r * SA_STR + c + 4]);
                af[mt][3] = f2tf32(sA[buf][(r + 8) * SA_STR + c + 4]);
            }
            #pragma unroll
            for (int nt = 0; nt < 4; nt++) {
                int n = wn + nt * 8 + g;
                int k = k8 * 8 + t;
                bf[nt][0] = f2tf32(sB[buf][k * SB_STR + n]);
                bf[nt][1] = f2tf32(sB[buf][(k + 4) * SB_STR + n]);
            }
            #pragma unroll
            for (int mt = 0; mt < 4; mt++)
                #pragma unroll
                for (int nt = 0; nt < 4; nt++)
                    mma_tf32(acc[mt][nt], af[mt], bf[nt]);
        }
        __syncthreads();
    }

    // Epilogue
    #pragma unroll
    for (int mt = 0; mt < 4; mt++) {
        #pragma unroll
        for (int nt = 0; nt < 4; nt++) {
            int r = bm + wm + mt * 16 + g;
            int c = bn + wn + nt * 8 + 2 * t;
            float b0 = bias[c], b1 = bias[c + 1];
            float v00 = acc[mt][nt][0] + b0;
            float v01 = acc[mt][nt][1] + b1;
            float v10 = acc[mt][nt][2] + b0;
            float v11 = acc[mt][nt][3] + b1;
            if (MODE == 1) {
                v00 = sigmoidf_(v00); v01 = sigmoidf_(v01);
                v10 = sigmoidf_(v10); v11 = sigmoidf_(v11);
            }
            if (MODE == 2) {
                float2 r0 = *(const float2*)&res[(size_t)r * N + c];
                float2 r1 = *(const float2*)&res[(size_t)(r + 8) * N + c];
                v00 += r0.x; v01 += r0.y; v10 += r1.x; v11 += r1.y;
            }
            float2 o0 = make_float2(v00, v01);
            float2 o1 = make_float2(v10, v11);
            *(float2*)&C[(size_t)r * N + c]       = o0;
            *(float2*)&C[(size_t)(r + 8) * N + c] = o1;
        }
    }
}

// ---------------------------------------------------------------------------
// Fused scan + mix: per (b,h) chain, 64 threads (one per ds).
//   delta = sigmoid(p[..,0,:]); h = delta*h + B; ssm = C*h
//   mixed = gate*ssm + (1-gate)*xn   (store)
//   h_last written at the end.
// ---------------------------------------------------------------------------
__global__ void scan_kernel(const float* __restrict__ p,
                            const float* __restrict__ gate,
                            const float* __restrict__ xn,
                            const float* __restrict__ st0,
                            float* __restrict__ mixed,
                            float* __restrict__ hlast, int L) {
    int b = blockIdx.x / Hh;
    int h = blockIdx.x % Hh;
    int s = threadIdx.x;

    float hst = st0[(size_t)blockIdx.x * DSs + s];

    const size_t pstr = (size_t)Hh * 3 * DSs;  // 6144
    const float* pb = p + ((size_t)b * L) * pstr + (size_t)h * 3 * DSs + s;
    size_t goff = ((size_t)b * L) * Dm + (size_t)h * DSs + s;
    const float* gb = gate + goff;
    const float* xb = xn + goff;
    float* mb = mixed + goff;

    const int U = 4;
    float dv[U], bv[U], cv[U], gv[U], xv[U];
    #pragma unroll
    for (int u = 0; u < U; u++) {
        const float* pp = pb + (size_t)u * pstr;
        dv[u] = __ldg(pp); bv[u] = __ldg(pp + DSs); cv[u] = __ldg(pp + 2 * DSs);
        gv[u] = __ldg(gb + (size_t)u * Dm);
        xv[u] = __ldg(xb + (size_t)u * Dm);
    }

    for (int l = 0; l < L; l += U) {
        float dn[U], bn2[U], cn[U], gn[U], xnv[U];
        if (l + U < L) {
            #pragma unroll
            for (int u = 0; u < U; u++) {
                const float* pp = pb + (size_t)(l + U + u) * pstr;
                dn[u] = __ldg(pp); bn2[u] = __ldg(pp + DSs); cn[u] = __ldg(pp + 2 * DSs);
                gn[u] = __ldg(gb + (size_t)(l + U + u) * Dm);
                xnv[u] = __ldg(xb + (size_t)(l + U + u) * Dm);
            }
        }
        #pragma unroll
        for (int u = 0; u < U; u++) {
            float dsg = 1.0f / (1.0f + __expf(-dv[u]));
            hst = fmaf(dsg, hst, bv[u]);
            float ssm = cv[u] * hst;
            // gate*ssm + (1-gate)*xn == xn + gate*(ssm - xn)
            mb[(size_t)(l + u) * Dm] = fmaf(gv[u], ssm - xv[u], xv[u]);
        }
        #pragma unroll
        for (int u = 0; u < U; u++) {
            dv[u] = dn[u]; bv[u] = bn2[u]; cv[u] = cn[u]; gv[u] = gn[u]; xv[u] = xnv[u];
        }
    }
    hlast[(size_t)blockIdx.x * DSs + s] = hst;
}

// ---------------------------------------------------------------------------
// Launch
// ---------------------------------------------------------------------------
extern "C" void kernel_launch(void* const* d_in, const int* in_sizes, int n_in,
                              void* d_out, int out_size) {
    const float* x      = (const float*)d_in[0];
    const float* state  = (const float*)d_in[1];
    const float* norm_w = (const float*)d_in[2];
    const float* conv_w = (const float*)d_in[3];
    const float* conv_b = (const float*)d_in[4];
    const float* pp_w   = (const float*)d_in[5];
    const float* pp_b   = (const float*)d_in[6];
    const float* gp_w   = (const float*)d_in[7];
    const float* gp_b   = (const float*)d_in[8];
    const float* op_w   = (const float*)d_in[9];
    const float* op_b   = (const float*)d_in[10];
    float* out = (float*)d_out;

    int BL = in_sizes[0] / Dm;                 // 8192
    int Bb = in_sizes[1] / (Hh * DSs);         // 2
    int L  = BL / Bb;                          // 4096

    float* scratch;
    cudaGetSymbolAddress((void**)&scratch, g_scratch);
    float* xn    = scratch + OFF_XN;
    float* xc    = scratch + OFF_XC;
    float* p     = scratch + OFF_P;
    float* gatep = scratch + OFF_GATE;
    float* mixed = scratch + OFF_MIXED;

    // 1) RMSNorm
    rmsnorm_kernel<<<BL, 256>>>(x, norm_w, xn);

    // 2) Causal conv + SiLU
    conv_silu_kernel<<<dim3(Dm / 128, L / 256, Bb), 128>>>(xn, conv_w, conv_b, xc, L);

    // 3) p = xn @ pp_w + pp_b   (M x 6144)
    gemm_tf32<0><<<dim3(P_COLS / GBN, BL / GBM), 256>>>(xn, pp_w, pp_b, nullptr, p,
                                                        BL, P_COLS, Dm);

    // 4) gate = sigmoid(xc @ gp_w + gp_b)
    gemm_tf32<1><<<dim3(Dm / GBN, BL / GBM), 256>>>(xc, gp_w, gp_b, nullptr, gatep,
                                                    BL, Dm, Dm);

    // 5) scan + mix  (also writes h_last to tail of output)
    scan_kernel<<<Bb * Hh, DSs>>>(p, gatep, xn, state, mixed,
                                  out + (size_t)BL * Dm, L);

    // 6) y = mixed @ op_w + op_b + x
    gemm_tf32<2><<<dim3(Dm / GBN, BL / GBM), 256>>>(mixed, op_w, op_b, x, out,
                                                    BL, Dm, Dm);
}

// round 5
// speedup vs baseline: 1.2928x; 1.2928x over previous
#include <cuda_runtime.h>
#include <cuda_bf16.h>
#include <cstdint>
#include <cstddef>
#include <math.h>

// Problem constants
#define Dm   2048
#define Hh   32
#define DSs  64
#define KK   4
#define EPSf 1e-6f
#define NC   32            // scan chunks

// Max sizes (B=2, L=4096)
#define BL_MAX  8192
#define P_COLS  (3*Dm)   // 6144
#define NB_MAX  64       // B*H chains

// Scratch layout (floats)
#define OFF_XN     ((size_t)0)
#define OFF_XC     ((size_t)BL_MAX*Dm)
#define OFF_P      (OFF_XC + (size_t)BL_MAX*Dm)
#define OFF_GATE   (OFF_P  + (size_t)BL_MAX*P_COLS)
#define OFF_MIXED  (OFF_GATE + (size_t)BL_MAX*Dm)
#define OFF_SCANA  (OFF_MIXED + (size_t)BL_MAX*Dm)
#define OFF_SCANH  (OFF_SCANA + (size_t)NB_MAX*NC*DSs)
#define OFF_SCANI  (OFF_SCANH + (size_t)NB_MAX*NC*DSs)
#define SCRATCH_FLOATS (OFF_SCANI + (size_t)NB_MAX*NC*DSs)

__device__ float g_scratch[SCRATCH_FLOATS];

// ---------------------------------------------------------------------------
// Helpers
// ---------------------------------------------------------------------------
__device__ __forceinline__ uint32_t f2tf32(float f) {
    uint32_t u;
    asm("cvt.rna.tf32.f32 %0, %1;" : "=r"(u) : "f"(f));
    return u;
}

__device__ __forceinline__ void mma_tf32(float* c, const uint32_t* a, const uint32_t* b) {
    asm volatile(
        "mma.sync.aligned.m16n8k8.row.col.f32.tf32.tf32.f32 "
        "{%0,%1,%2,%3}, {%4,%5,%6,%7}, {%8,%9}, {%0,%1,%2,%3};\n"
        : "+f"(c[0]), "+f"(c[1]), "+f"(c[2]), "+f"(c[3])
        : "r"(a[0]), "r"(a[1]), "r"(a[2]), "r"(a[3]),
          "r"(b[0]), "r"(b[1]));
}

__device__ __forceinline__ void cp_async16(void* smem, const void* gmem) {
    uint32_t s = (uint32_t)__cvta_generic_to_shared(smem);
    asm volatile("cp.async.cg.shared.global [%0], [%1], 16;\n" :: "r"(s), "l"(gmem));
}

__device__ __forceinline__ float sigmoidf_(float v) {
    return 1.0f / (1.0f + __expf(-v));
}

// ---------------------------------------------------------------------------
// RMSNorm
// ---------------------------------------------------------------------------
__global__ void rmsnorm_kernel(const float* __restrict__ x,
                               const float* __restrict__ w,
                               float* __restrict__ xn) {
    size_t row = blockIdx.x;
    const float4* xr = (const float4*)(x + row * Dm);
    float4 v0 = xr[threadIdx.x];
    float4 v1 = xr[threadIdx.x + 256];
    float ss = v0.x*v0.x + v0.y*v0.y + v0.z*v0.z + v0.w*v0.w
             + v1.x*v1.x + v1.y*v1.y + v1.z*v1.z + v1.w*v1.w;
    #pragma unroll
    for (int o = 16; o > 0; o >>= 1) ss += __shfl_xor_sync(0xffffffffu, ss, o);
    __shared__ float red[8];
    if ((threadIdx.x & 31) == 0) red[threadIdx.x >> 5] = ss;
    __syncthreads();
    float tot = red[0] + red[1] + red[2] + red[3] + red[4] + red[5] + red[6] + red[7];
    float inv = rsqrtf(tot * (1.0f / Dm) + EPSf);

    const float4* wr = (const float4*)w;
    float4 w0 = wr[threadIdx.x];
    float4 w1 = wr[threadIdx.x + 256];
    float4 o0, o1;
    o0.x = v0.x * w0.x * inv; o0.y = v0.y * w0.y * inv;
    o0.z = v0.z * w0.z * inv; o0.w = v0.w * w0.w * inv;
    o1.x = v1.x * w1.x * inv; o1.y = v1.y * w1.y * inv;
    o1.z = v1.z * w1.z * inv; o1.w = v1.w * w1.w * inv;
    float4* orow = (float4*)(xn + row * Dm);
    orow[threadIdx.x]       = o0;
    orow[threadIdx.x + 256] = o1;
}

// ---------------------------------------------------------------------------
// Causal depthwise conv (K=4) + SiLU
// ---------------------------------------------------------------------------
__global__ void conv_silu_kernel(const float* __restrict__ xn,
                                 const float* __restrict__ cw,
                                 const float* __restrict__ cb,
                                 float* __restrict__ xc, int L) {
    int d  = blockIdx.x * 128 + threadIdx.x;
    int b  = blockIdx.z;
    int l0 = blockIdx.y * 256;
    float w0 = cw[d*KK + 0], w1 = cw[d*KK + 1], w2 = cw[d*KK + 2], w3 = cw[d*KK + 3];
    float bb = cb[d];
    const float* base = xn + ((size_t)b * L) * Dm + d;
    float* obase      = xc + ((size_t)b * L) * Dm + d;

    float xm3 = (l0 >= 3) ? base[(size_t)(l0 - 3) * Dm] : 0.0f;
    float xm2 = (l0 >= 2) ? base[(size_t)(l0 - 2) * Dm] : 0.0f;
    float xm1 = (l0 >= 1) ? base[(size_t)(l0 - 1) * Dm] : 0.0f;

    #pragma unroll 8
    for (int l = l0; l < l0 + 256; l++) {
        float xcur = base[(size_t)l * Dm];
        float acc = bb + w0 * xm3 + w1 * xm2 + w2 * xm1 + w3 * xcur;
        float sv = acc * sigmoidf_(acc);
        obase[(size_t)l * Dm] = sv;
        xm3 = xm2; xm2 = xm1; xm1 = xcur;
    }
}

// ---------------------------------------------------------------------------
// TF32 GEMM, BK=32 double-buffered (dynamic smem)
//   MODE 0: +bias   MODE 1: sigmoid(+bias)   MODE 2: +bias+res
// Tiles: BM=128, BN=128, BK=32, 256 threads (8 warps of 64x32)
// ---------------------------------------------------------------------------
#define GBM 128
#define GBN 128
#define GBK 32
#define SA_STR 36    // 36 mod 32 = 4 -> conflict-free A fragment loads
#define SB_STR 136   // 136 mod 32 = 8 -> conflict-free B fragment loads
#define SA_ELEMS (GBM * SA_STR)   // 4608
#define SB_ELEMS (GBK * SB_STR)   // 4352
#define GEMM_SMEM_BYTES ((2*SA_ELEMS + 2*SB_ELEMS) * 4)   // 71680

template<int MODE>
__global__ __launch_bounds__(256, 2)
void gemm_tf32(const float* __restrict__ A, const float* __restrict__ Bw,
               const float* __restrict__ bias, const float* __restrict__ res,
               float* __restrict__ C, int M, int N, int K) {
    extern __shared__ float smem[];
    float* sA = smem;                   // [2][SA_ELEMS]
    float* sB = smem + 2 * SA_ELEMS;    // [2][SB_ELEMS]

    int tid  = threadIdx.x;
    int wid  = tid >> 5;
    int lane = tid & 31;
    int wm = (wid & 1) * 64;
    int wn = (wid >> 1) * 32;
    int g = lane >> 2;
    int t = lane & 3;

    int bm = blockIdx.y * GBM;
    int bn = blockIdx.x * GBN;

    const float* Aptr = A + (size_t)bm * K;
    const float* Bptr = Bw + bn;

    float acc[4][4][4];
    #pragma unroll
    for (int i = 0; i < 4; i++)
        #pragma unroll
        for (int j = 0; j < 4; j++)
            #pragma unroll
            for (int q = 0; q < 4; q++) acc[i][j][q] = 0.0f;

    // Loader coords: A tile 128x32 -> 4 cp.async16 per thread (rows tid>>3 + 32*i)
    int a_r0 = tid >> 3;            // 0..31
    int a_c0 = (tid & 7) * 4;       // 0..28
    // B tile 32x128 -> 4 cp.async16 per thread (rows tid>>5 + 8*i)
    int b_r0 = tid >> 5;            // 0..7
    int b_c0 = (tid & 31) * 4;

    int NK = K / GBK;

    // Prologue
    {
        #pragma unroll
        for (int i = 0; i < 4; i++) {
            int r = a_r0 + 32 * i;
            cp_async16(&sA[r * SA_STR + a_c0], Aptr + (size_t)r * K + a_c0);
        }
        #pragma unroll
        for (int i = 0; i < 4; i++) {
            int r = b_r0 + 8 * i;
            cp_async16(&sB[r * SB_STR + b_c0], Bptr + (size_t)r * N + b_c0);
        }
        asm volatile("cp.async.commit_group;\n" ::);
    }

    for (int kt = 0; kt < NK; kt++) {
        int buf = kt & 1;
        float* cA = sA + buf * SA_ELEMS;
        float* cB = sB + buf * SB_ELEMS;
        if (kt + 1 < NK) {
            int k0 = (kt + 1) * GBK;
            float* nA = sA + (buf ^ 1) * SA_ELEMS;
            float* nB = sB + (buf ^ 1) * SB_ELEMS;
            #pragma unroll
            for (int i = 0; i < 4; i++) {
                int r = a_r0 + 32 * i;
                cp_async16(&nA[r * SA_STR + a_c0], Aptr + (size_t)r * K + k0 + a_c0);
            }
            #pragma unroll
            for (int i = 0; i < 4; i++) {
                int r = b_r0 + 8 * i;
                cp_async16(&nB[r * SB_STR + b_c0], Bptr + (size_t)(k0 + r) * N + b_c0);
            }
            asm volatile("cp.async.commit_group;\n" ::);
            asm volatile("cp.async.wait_group 1;\n" ::);
        } else {
            asm volatile("cp.async.wait_group 0;\n" ::);
        }
        __syncthreads();

        #pragma unroll
        for (int k8 = 0; k8 < 4; k8++) {
            uint32_t af[4][4], bf[4][2];
            #pragma unroll
            for (int mt = 0; mt < 4; mt++) {
                int r = wm + mt * 16 + g;
                int c = k8 * 8 + t;
                af[mt][0] = f2tf32(cA[r * SA_STR + c]);
                af[mt][1] = f2tf32(cA[(r + 8) * SA_STR + c]);
                af[mt][2] = f2tf32(cA[r * SA_STR + c + 4]);
                af[mt][3] = f2tf32(cA[(r + 8) * SA_STR + c + 4]);
            }
            #pragma unroll
            for (int nt = 0; nt < 4; nt++) {
                int n = wn + nt * 8 + g;
                int k = k8 * 8 + t;
                bf[nt][0] = f2tf32(cB[k * SB_STR + n]);
                bf[nt][1] = f2tf32(cB[(k + 4) * SB_STR + n]);
            }
            #pragma unroll
            for (int mt = 0; mt < 4; mt++)
                #pragma unroll
                for (int nt = 0; nt < 4; nt++)
                    mma_tf32(acc[mt][nt], af[mt], bf[nt]);
        }
        __syncthreads();
    }

    // Epilogue
    #pragma unroll
    for (int mt = 0; mt < 4; mt++) {
        #pragma unroll
        for (int nt = 0; nt < 4; nt++) {
            int r = bm + wm + mt * 16 + g;
            int c = bn + wn + nt * 8 + 2 * t;
            float b0 = bias[c], b1 = bias[c + 1];
            float v00 = acc[mt][nt][0] + b0;
            float v01 = acc[mt][nt][1] + b1;
            float v10 = acc[mt][nt][2] + b0;
            float v11 = acc[mt][nt][3] + b1;
            if (MODE == 1) {
                v00 = sigmoidf_(v00); v01 = sigmoidf_(v01);
                v10 = sigmoidf_(v10); v11 = sigmoidf_(v11);
            }
            if (MODE == 2) {
                float2 r0 = *(const float2*)&res[(size_t)r * N + c];
                float2 r1 = *(const float2*)&res[(size_t)(r + 8) * N + c];
                v00 += r0.x; v01 += r0.y; v10 += r1.x; v11 += r1.y;
            }
            *(float2*)&C[(size_t)r * N + c]       = make_float2(v00, v01);
            *(float2*)&C[(size_t)(r + 8) * N + c] = make_float2(v10, v11);
        }
    }
}

// ---------------------------------------------------------------------------
// Chunked parallel scan.
// Pass 1: per (chain, chunk): A_c = prod(delta), h_loc = zero-init local scan end.
// Pass 2: per chain: scan over 32 chunk summaries -> h_in per chunk + h_last.
// Pass 3: per (chain, chunk): exact recurrence from h_in, write mixed.
// ---------------------------------------------------------------------------
__global__ void scan_p1(const float* __restrict__ p,
                        float* __restrict__ Ac, float* __restrict__ Hc,
                        int L, int CL) {
    int chain = blockIdx.x;          // 0..NB-1
    int chunk = blockIdx.y;          // 0..NC-1
    int b = chain / Hh;
    int h = chain % Hh;
    int s = threadIdx.x;

    const size_t pstr = (size_t)Hh * 3 * DSs;
    const float* pb = p + ((size_t)b * L + (size_t)chunk * CL) * pstr
                        + (size_t)h * 3 * DSs + s;

    float A = 1.0f, hl = 0.0f;
    for (int l = 0; l < CL; l += 4) {
        float d0 = __ldg(pb + (size_t)(l+0) * pstr);
        float d1 = __ldg(pb + (size_t)(l+1) * pstr);
        float d2 = __ldg(pb + (size_t)(l+2) * pstr);
        float d3 = __ldg(pb + (size_t)(l+3) * pstr);
        float b0 = __ldg(pb + (size_t)(l+0) * pstr + DSs);
        float b1 = __ldg(pb + (size_t)(l+1) * pstr + DSs);
        float b2 = __ldg(pb + (size_t)(l+2) * pstr + DSs);
        float b3 = __ldg(pb + (size_t)(l+3) * pstr + DSs);
        float s0 = sigmoidf_(d0), s1 = sigmoidf_(d1);
        float s2 = sigmoidf_(d2), s3 = sigmoidf_(d3);
        A *= s0; hl = fmaf(s0, hl, b0);
        A *= s1; hl = fmaf(s1, hl, b1);
        A *= s2; hl = fmaf(s2, hl, b2);
        A *= s3; hl = fmaf(s3, hl, b3);
    }
    size_t idx = ((size_t)chain * NC + chunk) * DSs + s;
    Ac[idx] = A;
    Hc[idx] = hl;
}

__global__ void scan_mid(const float* __restrict__ Ac, const float* __restrict__ Hc,
                         const float* __restrict__ st0,
                         float* __restrict__ hin, float* __restrict__ hlast) {
    int chain = blockIdx.x;
    int s = threadIdx.x;
    float h = st0[(size_t)chain * DSs + s];
    #pragma unroll
    for (int c = 0; c < NC; c++) {
        size_t idx = ((size_t)chain * NC + c) * DSs + s;
        hin[idx] = h;
        h = fmaf(Ac[idx], h, Hc[idx]);
    }
    hlast[(size_t)chain * DSs + s] = h;
}

__global__ void scan_p3(const float* __restrict__ p,
                        const float* __restrict__ gate,
                        const float* __restrict__ xn,
                        const float* __restrict__ hin,
                        float* __restrict__ mixed, int L, int CL) {
    int chain = blockIdx.x;
    int chunk = blockIdx.y;
    int b = chain / Hh;
    int h = chain % Hh;
    int s = threadIdx.x;

    float hst = hin[((size_t)chain * NC + chunk) * DSs + s];

    const size_t pstr = (size_t)Hh * 3 * DSs;
    size_t l0 = (size_t)chunk * CL;
    const float* pb = p + ((size_t)b * L + l0) * pstr + (size_t)h * 3 * DSs + s;
    size_t goff = ((size_t)b * L + l0) * Dm + (size_t)h * DSs + s;
    const float* gb = gate + goff;
    const float* xb = xn + goff;
    float* mb = mixed + goff;

    for (int l = 0; l < CL; l += 4) {
        float dv[4], bv[4], cv[4], gv[4], xv[4];
        #pragma unroll
        for (int u = 0; u < 4; u++) {
            const float* pp = pb + (size_t)(l + u) * pstr;
            dv[u] = __ldg(pp);
            bv[u] = __ldg(pp + DSs);
            cv[u] = __ldg(pp + 2 * DSs);
            gv[u] = __ldg(gb + (size_t)(l + u) * Dm);
            xv[u] = __ldg(xb + (size_t)(l + u) * Dm);
        }
        #pragma unroll
        for (int u = 0; u < 4; u++) {
            float dsg = sigmoidf_(dv[u]);
            hst = fmaf(dsg, hst, bv[u]);
            float ssm = cv[u] * hst;
            mb[(size_t)(l + u) * Dm] = fmaf(gv[u], ssm - xv[u], xv[u]);
        }
    }
}

// ---------------------------------------------------------------------------
// Launch
// ---------------------------------------------------------------------------
extern "C" void kernel_launch(void* const* d_in, const int* in_sizes, int n_in,
                              void* d_out, int out_size) {
    const float* x      = (const float*)d_in[0];
    const float* state  = (const float*)d_in[1];
    const float* norm_w = (const float*)d_in[2];
    const float* conv_w = (const float*)d_in[3];
    const float* conv_b = (const float*)d_in[4];
    const float* pp_w   = (const float*)d_in[5];
    const float* pp_b   = (const float*)d_in[6];
    const float* gp_w   = (const float*)d_in[7];
    const float* gp_b   = (const float*)d_in[8];
    const float* op_w   = (const float*)d_in[9];
    const float* op_b   = (const float*)d_in[10];
    float* out = (float*)d_out;

    int BL = in_sizes[0] / Dm;                 // 8192
    int Bb = in_sizes[1] / (Hh * DSs);         // 2
    int L  = BL / Bb;                          // 4096
    int NBc = Bb * Hh;                         // 64
    int CL  = L / NC;                          // 128

    static bool attr_done = false;
    if (!attr_done) {
        cudaFuncSetAttribute(gemm_tf32<0>, cudaFuncAttributeMaxDynamicSharedMemorySize, GEMM_SMEM_BYTES);
        cudaFuncSetAttribute(gemm_tf32<1>, cudaFuncAttributeMaxDynamicSharedMemorySize, GEMM_SMEM_BYTES);
        cudaFuncSetAttribute(gemm_tf32<2>, cudaFuncAttributeMaxDynamicSharedMemorySize, GEMM_SMEM_BYTES);
        attr_done = true;
    }

    float* scratch;
    cudaGetSymbolAddress((void**)&scratch, g_scratch);
    float* xn    = scratch + OFF_XN;
    float* xc    = scratch + OFF_XC;
    float* p     = scratch + OFF_P;
    float* gatep = scratch + OFF_GATE;
    float* mixed = scratch + OFF_MIXED;
    float* scanA = scratch + OFF_SCANA;
    float* scanH = scratch + OFF_SCANH;
    float* scanI = scratch + OFF_SCANI;

    // 1) RMSNorm
    rmsnorm_kernel<<<BL, 256>>>(x, norm_w, xn);

    // 2) Causal conv + SiLU
    conv_silu_kernel<<<dim3(Dm / 128, L / 256, Bb), 128>>>(xn, conv_w, conv_b, xc, L);

    // 3) p = xn @ pp_w + pp_b
    gemm_tf32<0><<<dim3(P_COLS / GBN, BL / GBM), 256, GEMM_SMEM_BYTES>>>(
        xn, pp_w, pp_b, nullptr, p, BL, P_COLS, Dm);

    // 4) gate = sigmoid(xc @ gp_w + gp_b)
    gemm_tf32<1><<<dim3(Dm / GBN, BL / GBM), 256, GEMM_SMEM_BYTES>>>(
        xc, gp_w, gp_b, nullptr, gatep, BL, Dm, Dm);

    // 5) scan (3 passes); h_last to tail of output
    scan_p1<<<dim3(NBc, NC), DSs>>>(p, scanA, scanH, L, CL);
    scan_mid<<<NBc, DSs>>>(scanA, scanH, state, scanI, out + (size_t)BL * Dm);
    scan_p3<<<dim3(NBc, NC), DSs>>>(p, gatep, xn, scanI, mixed, L, CL);

    // 6) y = mixed @ op_w + op_b + x
    gemm_tf32<2><<<dim3(Dm / GBN, BL / GBM), 256, GEMM_SMEM_BYTES>>>(
        mixed, op_w, op_b, x, out, BL, Dm, Dm);
}

// round 7
// speedup vs baseline: 1.4765x; 1.1421x over previous
#include <cuda_runtime.h>
#include <cuda_bf16.h>
#include <cstdint>
#include <cstddef>
#include <math.h>

// Problem constants
#define Dm   2048
#define Hh   32
#define DSs  64
#define KK   4
#define EPSf 1e-6f
#define NC   32            // scan chunks

// Max sizes (B=2, L=4096)
#define BL_MAX  8192
#define P_COLS  (3*Dm)   // 6144
#define NB_MAX  64       // B*H chains

// Scratch layout (floats)
#define OFF_XN     ((size_t)0)
#define OFF_XC     ((size_t)BL_MAX*Dm)
#define OFF_P      (OFF_XC + (size_t)BL_MAX*Dm)
#define OFF_GATE   (OFF_P  + (size_t)BL_MAX*P_COLS)
#define OFF_MIXED  (OFF_GATE + (size_t)BL_MAX*Dm)
#define OFF_SCANA  (OFF_MIXED + (size_t)BL_MAX*Dm)
#define OFF_SCANH  (OFF_SCANA + (size_t)NB_MAX*NC*DSs)
#define OFF_SCANI  (OFF_SCANH + (size_t)NB_MAX*NC*DSs)
#define OFF_PPR    (OFF_SCANI + (size_t)NB_MAX*NC*DSs)
#define OFF_GPR    (OFF_PPR + (size_t)P_COLS*Dm)
#define OFF_OPR    (OFF_GPR + (size_t)Dm*Dm)
#define SCRATCH_FLOATS (OFF_OPR + (size_t)Dm*Dm)

__device__ float g_scratch[SCRATCH_FLOATS];

// ---------------------------------------------------------------------------
// Helpers
// ---------------------------------------------------------------------------
__device__ __forceinline__ float rn_tf32(float v) {
    uint32_t u;
    asm("cvt.rna.tf32.f32 %0, %1;" : "=r"(u) : "f"(v));
    return __uint_as_float(u);
}

__device__ __forceinline__ void mma_tf32(float* c, const uint32_t* a, const uint32_t* b) {
    asm volatile(
        "mma.sync.aligned.m16n8k8.row.col.f32.tf32.tf32.f32 "
        "{%0,%1,%2,%3}, {%4,%5,%6,%7}, {%8,%9}, {%0,%1,%2,%3};\n"
        : "+f"(c[0]), "+f"(c[1]), "+f"(c[2]), "+f"(c[3])
        : "r"(a[0]), "r"(a[1]), "r"(a[2]), "r"(a[3]),
          "r"(b[0]), "r"(b[1]));
}

__device__ __forceinline__ void cp_async16(void* smem, const void* gmem) {
    uint32_t s = (uint32_t)__cvta_generic_to_shared(smem);
    asm volatile("cp.async.cg.shared.global [%0], [%1], 16;\n" :: "r"(s), "l"(gmem));
}

__device__ __forceinline__ float sigmoidf_(float v) {
    return 1.0f / (1.0f + __expf(-v));
}

// ---------------------------------------------------------------------------
// Weight tf32 round (grid-stride float4 copy)
// ---------------------------------------------------------------------------
__global__ void round_weights(const float* __restrict__ W, float* __restrict__ R,
                              int n4) {
    int i = blockIdx.x * blockDim.x + threadIdx.x;
    int stride = gridDim.x * blockDim.x;
    const float4* w4 = (const float4*)W;
    float4* r4 = (float4*)R;
    for (; i < n4; i += stride) {
        float4 v = w4[i];
        v.x = rn_tf32(v.x); v.y = rn_tf32(v.y);
        v.z = rn_tf32(v.z); v.w = rn_tf32(v.w);
        r4[i] = v;
    }
}

// ---------------------------------------------------------------------------
// RMSNorm (stores tf32-rounded xn)
// ---------------------------------------------------------------------------
__global__ void rmsnorm_kernel(const float* __restrict__ x,
                               const float* __restrict__ w,
                               float* __restrict__ xn) {
    size_t row = blockIdx.x;
    const float4* xr = (const float4*)(x + row * Dm);
    float4 v0 = xr[threadIdx.x];
    float4 v1 = xr[threadIdx.x + 256];
    float ss = v0.x*v0.x + v0.y*v0.y + v0.z*v0.z + v0.w*v0.w
             + v1.x*v1.x + v1.y*v1.y + v1.z*v1.z + v1.w*v1.w;
    #pragma unroll
    for (int o = 16; o > 0; o >>= 1) ss += __shfl_xor_sync(0xffffffffu, ss, o);
    __shared__ float red[8];
    if ((threadIdx.x & 31) == 0) red[threadIdx.x >> 5] = ss;
    __syncthreads();
    float tot = red[0] + red[1] + red[2] + red[3] + red[4] + red[5] + red[6] + red[7];
    float inv = rsqrtf(tot * (1.0f / Dm) + EPSf);

    const float4* wr = (const float4*)w;
    float4 w0 = wr[threadIdx.x];
    float4 w1 = wr[threadIdx.x + 256];
    float4 o0, o1;
    o0.x = rn_tf32(v0.x * w0.x * inv); o0.y = rn_tf32(v0.y * w0.y * inv);
    o0.z = rn_tf32(v0.z * w0.z * inv); o0.w = rn_tf32(v0.w * w0.w * inv);
    o1.x = rn_tf32(v1.x * w1.x * inv); o1.y = rn_tf32(v1.y * w1.y * inv);
    o1.z = rn_tf32(v1.z * w1.z * inv); o1.w = rn_tf32(v1.w * w1.w * inv);
    float4* orow = (float4*)(xn + row * Dm);
    orow[threadIdx.x]       = o0;
    orow[threadIdx.x + 256] = o1;
}

// ---------------------------------------------------------------------------
// Causal depthwise conv (K=4) + SiLU (stores tf32-rounded xc)
// ---------------------------------------------------------------------------
__global__ void conv_silu_kernel(const float* __restrict__ xn,
                                 const float* __restrict__ cw,
                                 const float* __restrict__ cb,
                                 float* __restrict__ xc, int L) {
    int d  = blockIdx.x * 128 + threadIdx.x;
    int b  = blockIdx.z;
    int l0 = blockIdx.y * 256;
    float w0 = cw[d*KK + 0], w1 = cw[d*KK + 1], w2 = cw[d*KK + 2], w3 = cw[d*KK + 3];
    float bb = cb[d];
    const float* base = xn + ((size_t)b * L) * Dm + d;
    float* obase      = xc + ((size_t)b * L) * Dm + d;

    float xm3 = (l0 >= 3) ? base[(size_t)(l0 - 3) * Dm] : 0.0f;
    float xm2 = (l0 >= 2) ? base[(size_t)(l0 - 2) * Dm] : 0.0f;
    float xm1 = (l0 >= 1) ? base[(size_t)(l0 - 1) * Dm] : 0.0f;

    #pragma unroll 8
    for (int l = l0; l < l0 + 256; l++) {
        float xcur = base[(size_t)l * Dm];
        float acc = bb + w0 * xm3 + w1 * xm2 + w2 * xm1 + w3 * xcur;
        float sv = acc * sigmoidf_(acc);
        obase[(size_t)l * Dm] = rn_tf32(sv);
        xm3 = xm2; xm2 = xm1; xm1 = xcur;
    }
}

// ---------------------------------------------------------------------------
// TF32 GEMM, BK=32 double-buffered (dynamic smem). Inputs PRE-ROUNDED to
// tf32 in memory, so fragments are loaded as raw u32 — no cvt in the loop.
//   MODE 0: +bias   MODE 1: sigmoid(+bias)   MODE 2: +bias+res
// Tiles: BM=128, BN=128, BK=32, 256 threads (8 warps of 64x32)
// ---------------------------------------------------------------------------
#define GBM 128
#define GBN 128
#define GBK 32
#define SA_STR 36    // 36 mod 32 = 4 -> conflict-free A fragment loads
#define SB_STR 136   // 136 mod 32 = 8 -> conflict-free B fragment loads
#define SA_ELEMS (GBM * SA_STR)   // 4608
#define SB_ELEMS (GBK * SB_STR)   // 4352
#define GEMM_SMEM_BYTES ((2*SA_ELEMS + 2*SB_ELEMS) * 4)   // 71680

template<int MODE>
__global__ __launch_bounds__(256, 2)
void gemm_tf32(const float* __restrict__ A, const float* __restrict__ Bw,
               const float* __restrict__ bias, const float* __restrict__ res,
               float* __restrict__ C, int M, int N, int K) {
    extern __shared__ float smem[];
    float* sA = smem;                   // [2][SA_ELEMS]
    float* sB = smem + 2 * SA_ELEMS;    // [2][SB_ELEMS]

    int tid  = threadIdx.x;
    int wid  = tid >> 5;
    int lane = tid & 31;
    int wm = (wid & 1) * 64;
    int wn = (wid >> 1) * 32;
    int g = lane >> 2;
    int t = lane & 3;

    int bm = blockIdx.y * GBM;
    int bn = blockIdx.x * GBN;

    const float* Aptr = A + (size_t)bm * K;
    const float* Bptr = Bw + bn;

    float acc[4][4][4];
    #pragma unroll
    for (int i = 0; i < 4; i++)
        #pragma unroll
        for (int j = 0; j < 4; j++)
            #pragma unroll
            for (int q = 0; q < 4; q++) acc[i][j][q] = 0.0f;

    int a_r0 = tid >> 3;            // 0..31
    int a_c0 = (tid & 7) * 4;       // 0..28
    int b_r0 = tid >> 5;            // 0..7
    int b_c0 = (tid & 31) * 4;

    int NK = K / GBK;

    // Prologue
    {
        #pragma unroll
        for (int i = 0; i < 4; i++) {
            int r = a_r0 + 32 * i;
            cp_async16(&sA[r * SA_STR + a_c0], Aptr + (size_t)r * K + a_c0);
        }
        #pragma unroll
        for (int i = 0; i < 4; i++) {
            int r = b_r0 + 8 * i;
            cp_async16(&sB[r * SB_STR + b_c0], Bptr + (size_t)r * N + b_c0);
        }
        asm volatile("cp.async.commit_group;\n" ::);
    }

    for (int kt = 0; kt < NK; kt++) {
        int buf = kt & 1;
        const uint32_t* cA = (const uint32_t*)(sA + buf * SA_ELEMS);
        const uint32_t* cB = (const uint32_t*)(sB + buf * SB_ELEMS);
        if (kt + 1 < NK) {
            int k0 = (kt + 1) * GBK;
            float* nA = sA + (buf ^ 1) * SA_ELEMS;
            float* nB = sB + (buf ^ 1) * SB_ELEMS;
            #pragma unroll
            for (int i = 0; i < 4; i++) {
                int r = a_r0 + 32 * i;
                cp_async16(&nA[r * SA_STR + a_c0], Aptr + (size_t)r * K + k0 + a_c0);
            }
            #pragma unroll
            for (int i = 0; i < 4; i++) {
                int r = b_r0 + 8 * i;
                cp_async16(&nB[r * SB_STR + b_c0], Bptr + (size_t)(k0 + r) * N + b_c0);
            }
            asm volatile("cp.async.commit_group;\n" ::);
            asm volatile("cp.async.wait_group 1;\n" ::);
        } else {
            asm volatile("cp.async.wait_group 0;\n" ::);
        }
        __syncthreads();

        #pragma unroll
        for (int k8 = 0; k8 < 4; k8++) {
            uint32_t af[4][4], bf[4][2];
            #pragma unroll
            for (int mt = 0; mt < 4; mt++) {
                int r = wm + mt * 16 + g;
                int c = k8 * 8 + t;
                af[mt][0] = cA[r * SA_STR + c];
                af[mt][1] = cA[(r + 8) * SA_STR + c];
                af[mt][2] = cA[r * SA_STR + c + 4];
                af[mt][3] = cA[(r + 8) * SA_STR + c + 4];
            }
            #pragma unroll
            for (int nt = 0; nt < 4; nt++) {
                int n = wn + nt * 8 + g;
                int k = k8 * 8 + t;
                bf[nt][0] = cB[k * SB_STR + n];
                bf[nt][1] = cB[(k + 4) * SB_STR + n];
            }
            #pragma unroll
            for (int mt = 0; mt < 4; mt++)
                #pragma unroll
                for (int nt = 0; nt < 4; nt++)
                    mma_tf32(acc[mt][nt], af[mt], bf[nt]);
        }
        __syncthreads();
    }

    // Epilogue
    #pragma unroll
    for (int mt = 0; mt < 4; mt++) {
        #pragma unroll
        for (int nt = 0; nt < 4; nt++) {
            int r = bm + wm + mt * 16 + g;
            int c = bn + wn + nt * 8 + 2 * t;
            float b0 = bias[c], b1 = bias[c + 1];
            float v00 = acc[mt][nt][0] + b0;
            float v01 = acc[mt][nt][1] + b1;
            float v10 = acc[mt][nt][2] + b0;
            float v11 = acc[mt][nt][3] + b1;
            if (MODE == 1) {
                v00 = sigmoidf_(v00); v01 = sigmoidf_(v01);
                v10 = sigmoidf_(v10); v11 = sigmoidf_(v11);
            }
            if (MODE == 2) {
                float2 r0 = *(const float2*)&res[(size_t)r * N + c];
                float2 r1 = *(const float2*)&res[(size_t)(r + 8) * N + c];
                v00 += r0.x; v01 += r0.y; v10 += r1.x; v11 += r1.y;
            }
            *(float2*)&C[(size_t)r * N + c]       = make_float2(v00, v01);
            *(float2*)&C[(size_t)(r + 8) * N + c] = make_float2(v10, v11);
        }
    }
}

// ---------------------------------------------------------------------------
// Chunked parallel scan (3 passes). scan_p3 stores tf32-rounded mixed.
// ---------------------------------------------------------------------------
__global__ void scan_p1(const float* __restrict__ p,
                        float* __restrict__ Ac, float* __restrict__ Hc,
                        int L, int CL) {
    int chain = blockIdx.x;
    int chunk = blockIdx.y;
    int b = chain / Hh;
    int h = chain % Hh;
    int s = threadIdx.x;

    const size_t pstr = (size_t)Hh * 3 * DSs;
    const float* pb = p + ((size_t)b * L + (size_t)chunk * CL) * pstr
                        + (size_t)h * 3 * DSs + s;

    float A = 1.0f, hl = 0.0f;
    for (int l = 0; l < CL; l += 4) {
        float d0 = __ldg(pb + (size_t)(l+0) * pstr);
        float d1 = __ldg(pb + (size_t)(l+1) * pstr);
        float d2 = __ldg(pb + (size_t)(l+2) * pstr);
        float d3 = __ldg(pb + (size_t)(l+3) * pstr);
        float b0 = __ldg(pb + (size_t)(l+0) * pstr + DSs);
        float b1 = __ldg(pb + (size_t)(l+1) * pstr + DSs);
        float b2 = __ldg(pb + (size_t)(l+2) * pstr + DSs);
        float b3 = __ldg(pb + (size_t)(l+3) * pstr + DSs);
        float s0 = sigmoidf_(d0), s1 = sigmoidf_(d1);
        float s2 = sigmoidf_(d2), s3 = sigmoidf_(d3);
        A *= s0; hl = fmaf(s0, hl, b0);
        A *= s1; hl = fmaf(s1, hl, b1);
        A *= s2; hl = fmaf(s2, hl, b2);
        A *= s3; hl = fmaf(s3, hl, b3);
    }
    size_t idx = ((size_t)chain * NC + chunk) * DSs + s;
    Ac[idx] = A;
    Hc[idx] = hl;
}

__global__ void scan_mid(const float* __restrict__ Ac, const float* __restrict__ Hc,
                         const float* __restrict__ st0,
                         float* __restrict__ hin, float* __restrict__ hlast) {
    int chain = blockIdx.x;
    int s = threadIdx.x;
    float h = st0[(size_t)chain * DSs + s];
    #pragma unroll
    for (int c = 0; c < NC; c++) {
        size_t idx = ((size_t)chain * NC + c) * DSs + s;
        hin[idx] = h;
        h = fmaf(Ac[idx], h, Hc[idx]);
    }
    hlast[(size_t)chain * DSs + s] = h;
}

__global__ void scan_p3(const float* __restrict__ p,
                        const float* __restrict__ gate,
                        const float* __restrict__ xn,
                        const float* __restrict__ hin,
                        float* __restrict__ mixed, int L, int CL) {
    int chain = blockIdx.x;
    int chunk = blockIdx.y;
    int b = chain / Hh;
    int h = chain % Hh;
    int s = threadIdx.x;

    float hst = hin[((size_t)chain * NC + chunk) * DSs + s];

    const size_t pstr = (size_t)Hh * 3 * DSs;
    size_t l0 = (size_t)chunk * CL;
    const float* pb = p + ((size_t)b * L + l0) * pstr + (size_t)h * 3 * DSs + s;
    size_t goff = ((size_t)b * L + l0) * Dm + (size_t)h * DSs + s;
    const float* gb = gate + goff;
    const float* xb = xn + goff;
    float* mb = mixed + goff;

    for (int l = 0; l < CL; l += 4) {
        float dv[4], bv[4], cv[4], gv[4], xv[4];
        #pragma unroll
        for (int u = 0; u < 4; u++) {
            const float* pp = pb + (size_t)(l + u) * pstr;
            dv[u] = __ldg(pp);
            bv[u] = __ldg(pp + DSs);
            cv[u] = __ldg(pp + 2 * DSs);
            gv[u] = __ldg(gb + (size_t)(l + u) * Dm);
            xv[u] = __ldg(xb + (size_t)(l + u) * Dm);
        }
        #pragma unroll
        for (int u = 0; u < 4; u++) {
            float dsg = sigmoidf_(dv[u]);
            hst = fmaf(dsg, hst, bv[u]);
            float ssm = cv[u] * hst;
            mb[(size_t)(l + u) * Dm] = rn_tf32(fmaf(gv[u], ssm - xv[u], xv[u]));
        }
    }
}

// ---------------------------------------------------------------------------
// Launch
// ---------------------------------------------------------------------------
extern "C" void kernel_launch(void* const* d_in, const int* in_sizes, int n_in,
                              void* d_out, int out_size) {
    const float* x      = (const float*)d_in[0];
    const float* state  = (const float*)d_in[1];
    const float* norm_w = (const float*)d_in[2];
    const float* conv_w = (const float*)d_in[3];
    const float* conv_b = (const float*)d_in[4];
    const float* pp_w   = (const float*)d_in[5];
    const float* pp_b   = (const float*)d_in[6];
    const float* gp_w   = (const float*)d_in[7];
    const float* gp_b   = (const float*)d_in[8];
    const float* op_w   = (const float*)d_in[9];
    const float* op_b   = (const float*)d_in[10];
    float* out = (float*)d_out;

    int BL = in_sizes[0] / Dm;                 // 8192
    int Bb = in_sizes[1] / (Hh * DSs);         // 2
    int L  = BL / Bb;                          // 4096
    int NBc = Bb * Hh;                         // 64
    int CL  = L / NC;                          // 128

    static bool attr_done = false;
    if (!attr_done) {
        cudaFuncSetAttribute(gemm_tf32<0>, cudaFuncAttributeMaxDynamicSharedMemorySize, GEMM_SMEM_BYTES);
        cudaFuncSetAttribute(gemm_tf32<1>, cudaFuncAttributeMaxDynamicSharedMemorySize, GEMM_SMEM_BYTES);
        cudaFuncSetAttribute(gemm_tf32<2>, cudaFuncAttributeMaxDynamicSharedMemorySize, GEMM_SMEM_BYTES);
        attr_done = true;
    }

    float* scratch;
    cudaGetSymbolAddress((void**)&scratch, g_scratch);
    float* xn    = scratch + OFF_XN;
    float* xc    = scratch + OFF_XC;
    float* p     = scratch + OFF_P;
    float* gatep = scratch + OFF_GATE;
    float* mixed = scratch + OFF_MIXED;
    float* scanA = scratch + OFF_SCANA;
    float* scanH = scratch + OFF_SCANH;
    float* scanI = scratch + OFF_SCANI;
    float* ppR   = scratch + OFF_PPR;
    float* gpR   = scratch + OFF_GPR;
    float* opR   = scratch + OFF_OPR;

    // 0) Weight tf32 rounding (removes cvt from GEMM inner loops)
    round_weights<<<1184, 256>>>(pp_w, ppR, (Dm * P_COLS) / 4);
    round_weights<<<1184, 256>>>(gp_w, gpR, (Dm * Dm) / 4);
    round_weights<<<1184, 256>>>(op_w, opR, (Dm * Dm) / 4);

    // 1) RMSNorm (tf32-rounded xn)
    rmsnorm_kernel<<<BL, 256>>>(x, norm_w, xn);

    // 2) Causal conv + SiLU (tf32-rounded xc)
    conv_silu_kernel<<<dim3(Dm / 128, L / 256, Bb), 128>>>(xn, conv_w, conv_b, xc, L);

    // 3) p = xn @ pp_w + pp_b
    gemm_tf32<0><<<dim3(P_COLS / GBN, BL / GBM), 256, GEMM_SMEM_BYTES>>>(
        xn, ppR, pp_b, nullptr, p, BL, P_COLS, Dm);

    // 4) gate = sigmoid(xc @ gp_w + gp_b)
    gemm_tf32<1><<<dim3(Dm / GBN, BL / GBM), 256, GEMM_SMEM_BYTES>>>(
        xc, gpR, gp_b, nullptr, gatep, BL, Dm, Dm);

    // 5) scan (3 passes); h_last to tail of output
    scan_p1<<<dim3(NBc, NC), DSs>>>(p, scanA, scanH, L, CL);
    scan_mid<<<NBc, DSs>>>(scanA, scanH, state, scanI, out + (size_t)BL * Dm);
    scan_p3<<<dim3(NBc, NC), DSs>>>(p, gatep, xn, scanI, mixed, L, CL);

    // 6) y = mixed @ op_w + op_b + x
    gemm_tf32<2><<<dim3(Dm / GBN, BL / GBM), 256, GEMM_SMEM_BYTES>>>(
        mixed, opR, op_b, x, out, BL, Dm, Dm);
}